// round 1
// baseline (speedup 1.0000x reference)
#include <cuda_runtime.h>
#include <math.h>

#define NB 4
#define FB 32
#define HIN 1024
#define CIN 8
#define DD 64
#define WW 7
#define HO 1018
#define HP 1024
#define NSLICE (NB*FB)

// Scratch (zero-initialized at module load; padded regions never written -> stay 0)
__device__ float g_q1[(size_t)NSLICE * HP * DD];
__device__ float g_q2[(size_t)NSLICE * HP * DD];
__device__ float g_att[(size_t)NSLICE * HP * HP];
__device__ float g_p1[(size_t)NSLICE * HP * DD];

// ---------------------------------------------------------------------------
// Projection: q[n,f,h,d] = sum_{c,j} x[n,h+j,c,d] * W[f,c,d,j]
// grid (ceil(1018/32)=32, F=32, N=4), 256 threads
// ---------------------------------------------------------------------------
__global__ __launch_bounds__(256) void proj_kernel(const float* __restrict__ x,
                                                   const float* __restrict__ W,
                                                   int which)
{
    __shared__ float Ws[CIN * DD * WW];  // 3584 floats = 14KB, W[f] slice
    const int f = blockIdx.y, n = blockIdx.z;
    const float* Wf = W + (size_t)f * CIN * DD * WW;
    for (int i = threadIdx.x; i < CIN * DD * WW; i += 256) Ws[i] = Wf[i];
    __syncthreads();

    float* q = which ? g_q2 : g_q1;
    const int h0 = blockIdx.x * 32;
#pragma unroll
    for (int r = 0; r < 8; r++) {
        int idx = threadIdx.x + r * 256;   // 0..2047 over (hl, d)
        int hl = idx >> 6, d = idx & 63;
        int h = h0 + hl;
        if (h >= HO) continue;
        const float* xb = x + ((size_t)(n * HIN + h) * CIN) * DD + d;
        float acc = 0.f;
#pragma unroll
        for (int j = 0; j < WW; j++)
#pragma unroll
            for (int c = 0; c < CIN; c++)
                acc += xb[(j * CIN + c) * DD] * Ws[(c * DD + d) * WW + j];
        q[((size_t)(n * FB + f) * HP + h) * DD + d] = acc;
    }
}

// ---------------------------------------------------------------------------
// att[slice][h][g] = (1/1018) * sum_d q1[slice][h][d] * q2[slice][g][d]
// grid (16 g-tiles, 16 h-tiles, 128 slices), 256 threads, 64x64 tile, K=64
// ---------------------------------------------------------------------------
__global__ __launch_bounds__(256) void att_kernel()
{
    __shared__ __align__(16) float As[DD][68];  // [k][m], pad 68
    __shared__ __align__(16) float Bs[DD][68];  // [k][g]
    const int slice = blockIdx.z;
    const float* A = g_q1 + ((size_t)slice * HP + blockIdx.y * 64) * DD;
    const float* B = g_q2 + ((size_t)slice * HP + blockIdx.x * 64) * DD;
    const int tid = threadIdx.x;

#pragma unroll
    for (int i = 0; i < 4; i++) {
        int v = tid + i * 256;          // 0..1023 float4 slots per tile
        int m = v >> 4;                 // row 0..63
        int k4 = (v & 15) * 4;          // k 0..60
        float4 a = *(const float4*)(A + m * DD + k4);
        As[k4 + 0][m] = a.x; As[k4 + 1][m] = a.y;
        As[k4 + 2][m] = a.z; As[k4 + 3][m] = a.w;
        float4 b = *(const float4*)(B + m * DD + k4);
        Bs[k4 + 0][m] = b.x; Bs[k4 + 1][m] = b.y;
        Bs[k4 + 2][m] = b.z; Bs[k4 + 3][m] = b.w;
    }
    __syncthreads();

    const int ty = tid >> 4, tx = tid & 15;
    float acc[4][4] = {};
#pragma unroll 8
    for (int k = 0; k < DD; k++) {
        float4 a4 = *(const float4*)&As[k][ty * 4];
        float4 b4 = *(const float4*)&Bs[k][tx * 4];
        float av[4] = {a4.x, a4.y, a4.z, a4.w};
        float bv[4] = {b4.x, b4.y, b4.z, b4.w};
#pragma unroll
        for (int i = 0; i < 4; i++)
#pragma unroll
            for (int j = 0; j < 4; j++) acc[i][j] += av[i] * bv[j];
    }

    const float sc = 1.0f / 1018.0f;
    float* C = g_att + (size_t)slice * HP * HP
             + (size_t)(blockIdx.y * 64 + ty * 4) * HP + blockIdx.x * 64 + tx * 4;
#pragma unroll
    for (int i = 0; i < 4; i++) {
        float4 o = make_float4(acc[i][0] * sc, acc[i][1] * sc,
                               acc[i][2] * sc, acc[i][3] * sc);
        *(float4*)(C + (size_t)i * HP) = o;
    }
}

// ---------------------------------------------------------------------------
// Row softmax over g in [0,1018); cols [1018,1024) set to 0.
// grid = 128*1024 rows, 256 threads; row (1024 floats) held in registers.
// ---------------------------------------------------------------------------
__global__ __launch_bounds__(256) void softmax_kernel()
{
    __shared__ float red[8];
    const size_t row = blockIdx.x;
    float* p = g_att + row * HP;
    const int tid = threadIdx.x;
    float4 v = ((const float4*)p)[tid];
    const int c0 = tid * 4;
    const bool k0 = (c0 + 0) < HO, k1 = (c0 + 1) < HO,
               k2 = (c0 + 2) < HO, k3 = (c0 + 3) < HO;

    float mx = -1e30f;
    if (k0) mx = fmaxf(mx, v.x);
    if (k1) mx = fmaxf(mx, v.y);
    if (k2) mx = fmaxf(mx, v.z);
    if (k3) mx = fmaxf(mx, v.w);
#pragma unroll
    for (int o = 16; o; o >>= 1) mx = fmaxf(mx, __shfl_xor_sync(~0u, mx, o));
    if ((tid & 31) == 0) red[tid >> 5] = mx;
    __syncthreads();
    float M = red[0];
#pragma unroll
    for (int i = 1; i < 8; i++) M = fmaxf(M, red[i]);
    __syncthreads();  // red reads complete before reuse

    float4 e;
    e.x = k0 ? __expf(v.x - M) : 0.f;
    e.y = k1 ? __expf(v.y - M) : 0.f;
    e.z = k2 ? __expf(v.z - M) : 0.f;
    e.w = k3 ? __expf(v.w - M) : 0.f;
    float s = e.x + e.y + e.z + e.w;
#pragma unroll
    for (int o = 16; o; o >>= 1) s += __shfl_xor_sync(~0u, s, o);
    if ((tid & 31) == 0) red[tid >> 5] = s;
    __syncthreads();
    float S = red[0];
#pragma unroll
    for (int i = 1; i < 8; i++) S += red[i];
    float inv = 1.0f / S;

    e.x *= inv; e.y *= inv; e.z *= inv; e.w *= inv;
    ((float4*)p)[tid] = e;
}

// ---------------------------------------------------------------------------
// p = a @ V  (V = q2 for phase 0, V = p1 for phase 1), M=1024 rows, N=64, K=1024
// phase 0: store raw p1 (all rows) + tanh->out1 (h<1018)
// phase 1: tanh->out2 (h<1018)
// grid (16 row-tiles, 128 slices), 256 threads, BK=16
// ---------------------------------------------------------------------------
__global__ __launch_bounds__(256) void pv_kernel(float* __restrict__ out, int phase)
{
    __shared__ __align__(16) float As[16][68];  // [k][m]
    __shared__ __align__(16) float Bs[16][68];  // [k][d]
    const int slice = blockIdx.y;
    const int m0 = blockIdx.x * 64;
    const float* A = g_att + (size_t)slice * HP * HP + (size_t)m0 * HP;
    const float* B = (phase ? g_p1 : g_q2) + (size_t)slice * HP * DD;
    const int tid = threadIdx.x;
    const int ty = tid >> 4, tx = tid & 15;
    const int am = tid >> 2, ak = (tid & 3) * 4;       // A-load: 64 rows x 16 k
    const int bk = tid >> 4, bn = (tid & 15) * 4;      // B-load: 16 k x 64 d

    float acc[4][4] = {};
    for (int kk = 0; kk < HP; kk += 16) {
        __syncthreads();
        float4 a = *(const float4*)(A + (size_t)am * HP + kk + ak);
        As[ak + 0][am] = a.x; As[ak + 1][am] = a.y;
        As[ak + 2][am] = a.z; As[ak + 3][am] = a.w;
        *(float4*)&Bs[bk][bn] = *(const float4*)(B + (size_t)(kk + bk) * DD + bn);
        __syncthreads();
#pragma unroll
        for (int k = 0; k < 16; k++) {
            float4 a4 = *(const float4*)&As[k][ty * 4];
            float4 b4 = *(const float4*)&Bs[k][tx * 4];
            float av[4] = {a4.x, a4.y, a4.z, a4.w};
            float bv[4] = {b4.x, b4.y, b4.z, b4.w};
#pragma unroll
            for (int i = 0; i < 4; i++)
#pragma unroll
                for (int j = 0; j < 4; j++) acc[i][j] += av[i] * bv[j];
        }
    }

    const int n = slice >> 5, f = slice & 31;
    const int d = tx * 4;
#pragma unroll
    for (int i = 0; i < 4; i++) {
        int h = m0 + ty * 4 + i;
        if (!phase) {
            *(float4*)(g_p1 + ((size_t)slice * HP + h) * DD + d) =
                make_float4(acc[i][0], acc[i][1], acc[i][2], acc[i][3]);
        }
        if (h < HO) {
            float4 o = make_float4(tanhf(acc[i][0]), tanhf(acc[i][1]),
                                   tanhf(acc[i][2]), tanhf(acc[i][3]));
            *(float4*)(out + (((size_t)(n * HO + h) * FB + f) * DD + d)) = o;
        }
    }
}

// ---------------------------------------------------------------------------
extern "C" void kernel_launch(void* const* d_in, const int* in_sizes, int n_in,
                              void* d_out, int out_size)
{
    const float* prot1 = (const float*)d_in[0];
    const float* prot2 = (const float*)d_in[1];
    const float* W     = (const float*)d_in[2];
    float* out = (float*)d_out;

    proj_kernel<<<dim3(32, FB, NB), 256>>>(prot1, W, 0);
    proj_kernel<<<dim3(32, FB, NB), 256>>>(prot2, W, 1);
    att_kernel<<<dim3(16, 16, NSLICE), 256>>>();
    softmax_kernel<<<NSLICE * HP, 256>>>();
    pv_kernel<<<dim3(16, NSLICE), 256>>>(out, 0);
    pv_kernel<<<dim3(16, NSLICE), 256>>>(out + (size_t)NB * HO * FB * DD, 1);
}

// round 3
// speedup vs baseline: 1.6097x; 1.6097x over previous
#include <cuda_runtime.h>
#include <math.h>

#define NB 4
#define FB 32
#define HIN 1024
#define CIN 8
#define DD 64
#define WW 7
#define HO 1018
#define HP 1024
#define NSLICE (NB*FB)

// Scratch (zero-initialized at module load; padded regions never written -> stay 0)
__device__ float g_q1[(size_t)NSLICE * HP * DD];
__device__ float g_q2[(size_t)NSLICE * HP * DD];
__device__ float g_att[(size_t)NSLICE * HP * HP];
__device__ float g_p1[(size_t)NSLICE * HP * DD];

// ---------------------------------------------------------------------------
// tf32 helpers
// ---------------------------------------------------------------------------
__device__ __forceinline__ unsigned f2tf(float x) {
    unsigned u;
    asm("cvt.rna.tf32.f32 %0, %1;" : "=r"(u) : "f"(x));
    return u;
}

// D += A*B, m16n8k8 tf32
__device__ __forceinline__ void mma8(float* d, const unsigned* a, const unsigned* b) {
    asm volatile(
        "mma.sync.aligned.m16n8k8.row.col.f32.tf32.tf32.f32 "
        "{%0,%1,%2,%3},{%4,%5,%6,%7},{%8,%9},{%0,%1,%2,%3};"
        : "+f"(d[0]), "+f"(d[1]), "+f"(d[2]), "+f"(d[3])
        : "r"(a[0]), "r"(a[1]), "r"(a[2]), "r"(a[3]), "r"(b[0]), "r"(b[1]));
}

// Swizzled smem element read: tile row-major [row][ldk], col swizzled per
// 4-float group: phys_col = ((k&~3) ^ ((row&7)<<2)) | (k&3)
__device__ __forceinline__ unsigned lds_sw(const unsigned* base, int row, int k, int ldk) {
    return base[row * ldk + ((((k & ~3) ^ ((row & 7) << 2))) | (k & 3))];
}

// ---------------------------------------------------------------------------
// Projection: q[n,f,h,d] = sum_{c,j} x[n,h+j,c,d] * W[f,c,d,j]
// ---------------------------------------------------------------------------
__global__ __launch_bounds__(256) void proj_kernel(const float* __restrict__ x,
                                                   const float* __restrict__ W,
                                                   int which)
{
    __shared__ float Ws[CIN * DD * WW];
    const int f = blockIdx.y, n = blockIdx.z;
    const float* Wf = W + (size_t)f * CIN * DD * WW;
    for (int i = threadIdx.x; i < CIN * DD * WW; i += 256) Ws[i] = Wf[i];
    __syncthreads();

    float* q = which ? g_q2 : g_q1;
    const int h0 = blockIdx.x * 32;
#pragma unroll
    for (int r = 0; r < 8; r++) {
        int idx = threadIdx.x + r * 256;
        int hl = idx >> 6, d = idx & 63;
        int h = h0 + hl;
        if (h >= HO) continue;
        const float* xb = x + ((size_t)(n * HIN + h) * CIN) * DD + d;
        float acc = 0.f;
#pragma unroll
        for (int j = 0; j < WW; j++)
#pragma unroll
            for (int c = 0; c < CIN; c++)
                acc += xb[(j * CIN + c) * DD] * Ws[(c * DD + d) * WW + j];
        q[((size_t)(n * FB + f) * HP + h) * DD + d] = acc;
    }
}

// ---------------------------------------------------------------------------
// att (tf32 mma): 128x128 tile, K=64. grid (8,8,128), 256 thr = 8 warps (2m x 4n),
// warp tile 64x32.
// ---------------------------------------------------------------------------
extern __shared__ unsigned smem_att[];   // As[128*64] ++ Bs[128*64] = 64KB

__global__ __launch_bounds__(256) void att_kernel()
{
    unsigned* As = smem_att;
    unsigned* Bs = smem_att + 128 * 64;
    const int slice = blockIdx.z;
    const float* A = g_q1 + ((size_t)slice * HP + blockIdx.y * 128) * DD;
    const float* B = g_q2 + ((size_t)slice * HP + blockIdx.x * 128) * DD;
    const int tid = threadIdx.x;

#pragma unroll
    for (int r = 0; r < 8; r++) {
        int v = tid + r * 256;           // 2048 float4 slots per tile
        int m = v >> 4, k4 = (v & 15) << 2;
        int c4 = k4 ^ ((m & 7) << 2);
        float4 a = *(const float4*)(A + m * DD + k4);
        uint4 pa = make_uint4(f2tf(a.x), f2tf(a.y), f2tf(a.z), f2tf(a.w));
        *(uint4*)&As[m * 64 + c4] = pa;
        float4 b = *(const float4*)(B + m * DD + k4);
        uint4 pb = make_uint4(f2tf(b.x), f2tf(b.y), f2tf(b.z), f2tf(b.w));
        *(uint4*)&Bs[m * 64 + c4] = pb;
    }
    __syncthreads();

    const int warp = tid >> 5, lane = tid & 31;
    const int g = lane >> 2, i = lane & 3;
    const int wm = (warp >> 2) * 64;     // 2 warps in m
    const int wn = (warp & 3) * 32;      // 4 warps in n

    float acc[4][4][4] = {};
#pragma unroll
    for (int k0 = 0; k0 < DD; k0 += 8) {
        unsigned af[4][4], bf[4][2];
#pragma unroll
        for (int mf = 0; mf < 4; mf++) {
            int m = wm + mf * 16 + g;
            af[mf][0] = lds_sw(As, m,     k0 + i,     64);
            af[mf][1] = lds_sw(As, m + 8, k0 + i,     64);
            af[mf][2] = lds_sw(As, m,     k0 + 4 + i, 64);
            af[mf][3] = lds_sw(As, m + 8, k0 + 4 + i, 64);
        }
#pragma unroll
        for (int nf = 0; nf < 4; nf++) {
            int n = wn + nf * 8 + g;
            bf[nf][0] = lds_sw(Bs, n, k0 + i,     64);
            bf[nf][1] = lds_sw(Bs, n, k0 + 4 + i, 64);
        }
#pragma unroll
        for (int mf = 0; mf < 4; mf++)
#pragma unroll
            for (int nf = 0; nf < 4; nf++)
                mma8(acc[mf][nf], af[mf], bf[nf]);
    }

    const float sc = 1.0f / 1018.0f;
    float* C = g_att + (size_t)slice * HP * HP
             + (size_t)(blockIdx.y * 128 + wm) * HP + blockIdx.x * 128 + wn;
#pragma unroll
    for (int mf = 0; mf < 4; mf++) {
#pragma unroll
        for (int nf = 0; nf < 4; nf++) {
            int r0 = mf * 16 + g;
            int cc = nf * 8 + 2 * i;
            *(float2*)(C + (size_t)r0 * HP + cc) =
                make_float2(acc[mf][nf][0] * sc, acc[mf][nf][1] * sc);
            *(float2*)(C + (size_t)(r0 + 8) * HP + cc) =
                make_float2(acc[mf][nf][2] * sc, acc[mf][nf][3] * sc);
        }
    }
}

// ---------------------------------------------------------------------------
// Row softmax (unchanged; at DRAM bandwidth)
// ---------------------------------------------------------------------------
__global__ __launch_bounds__(256) void softmax_kernel()
{
    __shared__ float red[8];
    const size_t row = blockIdx.x;
    float* p = g_att + row * HP;
    const int tid = threadIdx.x;
    float4 v = ((const float4*)p)[tid];
    const int c0 = tid * 4;
    const bool k0 = (c0 + 0) < HO, k1 = (c0 + 1) < HO,
               k2 = (c0 + 2) < HO, k3 = (c0 + 3) < HO;

    float mx = -1e30f;
    if (k0) mx = fmaxf(mx, v.x);
    if (k1) mx = fmaxf(mx, v.y);
    if (k2) mx = fmaxf(mx, v.z);
    if (k3) mx = fmaxf(mx, v.w);
#pragma unroll
    for (int o = 16; o; o >>= 1) mx = fmaxf(mx, __shfl_xor_sync(~0u, mx, o));
    if ((tid & 31) == 0) red[tid >> 5] = mx;
    __syncthreads();
    float M = red[0];
#pragma unroll
    for (int i = 1; i < 8; i++) M = fmaxf(M, red[i]);
    __syncthreads();

    float4 e;
    e.x = k0 ? __expf(v.x - M) : 0.f;
    e.y = k1 ? __expf(v.y - M) : 0.f;
    e.z = k2 ? __expf(v.z - M) : 0.f;
    e.w = k3 ? __expf(v.w - M) : 0.f;
    float s = e.x + e.y + e.z + e.w;
#pragma unroll
    for (int o = 16; o; o >>= 1) s += __shfl_xor_sync(~0u, s, o);
    if ((tid & 31) == 0) red[tid >> 5] = s;
    __syncthreads();
    float S = red[0];
#pragma unroll
    for (int i = 1; i < 8; i++) S += red[i];
    float inv = 1.0f / S;

    e.x *= inv; e.y *= inv; e.z *= inv; e.w *= inv;
    ((float4*)p)[tid] = e;
}

// ---------------------------------------------------------------------------
// p = a @ V (tf32 mma). M-tile 256, N=64, BK=32. grid (4,128), 256 thr,
// 8 warps (4m x 2n), warp tile 64x32.
// phase 0: V=q2, store raw p1 + tanh->out1; phase 1: V=p1, tanh->out2.
// ---------------------------------------------------------------------------
__global__ __launch_bounds__(256) void pv_kernel(float* __restrict__ out, int phase)
{
    __shared__ unsigned As[256 * 32];   // swizzled [m][k]
    __shared__ unsigned Bs[32 * 72];    // natural [k][n], ld 72 (pad)
    const int slice = blockIdx.y;
    const int m0 = blockIdx.x * 256;
    const float* A = g_att + (size_t)slice * HP * HP + (size_t)m0 * HP;
    const float* V = (phase ? g_p1 : g_q2) + (size_t)slice * HP * DD;
    const int tid = threadIdx.x, warp = tid >> 5, lane = tid & 31;
    const int g = lane >> 2, i = lane & 3;
    const int wm = (warp >> 1) * 64, wn = (warp & 1) * 32;

    float acc[4][4][4] = {};
    for (int kk = 0; kk < HP; kk += 32) {
        __syncthreads();
        // A: 256x32 = 2048 float4 slots, 8 per thread
#pragma unroll
        for (int r = 0; r < 8; r++) {
            int v = tid + r * 256;
            int m = v >> 3, k4 = (v & 7) << 2;
            float4 a = *(const float4*)(A + (size_t)m * HP + kk + k4);
            int c4 = k4 ^ ((m & 7) << 2);
            uint4 p = make_uint4(f2tf(a.x), f2tf(a.y), f2tf(a.z), f2tf(a.w));
            *(uint4*)&As[m * 32 + c4] = p;
        }
        // B: 32x64 = 512 float4 slots, 2 per thread
#pragma unroll
        for (int r = 0; r < 2; r++) {
            int v = tid + r * 256;
            int k = v >> 4, n4 = (v & 15) << 2;
            float4 b = *(const float4*)(V + (size_t)(kk + k) * DD + n4);
            uint4 p = make_uint4(f2tf(b.x), f2tf(b.y), f2tf(b.z), f2tf(b.w));
            *(uint4*)&Bs[k * 72 + n4] = p;
        }
        __syncthreads();

#pragma unroll
        for (int k0 = 0; k0 < 32; k0 += 8) {
            unsigned af[4][4], bf[4][2];
#pragma unroll
            for (int mf = 0; mf < 4; mf++) {
                int m = wm + mf * 16 + g;
                af[mf][0] = lds_sw(As, m,     k0 + i,     32);
                af[mf][1] = lds_sw(As, m + 8, k0 + i,     32);
                af[mf][2] = lds_sw(As, m,     k0 + 4 + i, 32);
                af[mf][3] = lds_sw(As, m + 8, k0 + 4 + i, 32);
            }
#pragma unroll
            for (int nf = 0; nf < 4; nf++) {
                int n = wn + nf * 8 + g;
                bf[nf][0] = Bs[(k0 + i) * 72 + n];
                bf[nf][1] = Bs[(k0 + 4 + i) * 72 + n];
            }
#pragma unroll
            for (int mf = 0; mf < 4; mf++)
#pragma unroll
                for (int nf = 0; nf < 4; nf++)
                    mma8(acc[mf][nf], af[mf], bf[nf]);
        }
    }

    const int nb = slice >> 5, f = slice & 31;
#pragma unroll
    for (int mf = 0; mf < 4; mf++) {
#pragma unroll
        for (int nf = 0; nf < 4; nf++) {
            int d = wn + nf * 8 + 2 * i;
#pragma unroll
            for (int half = 0; half < 2; half++) {
                int h = m0 + wm + mf * 16 + g + half * 8;
                float v0 = acc[mf][nf][half * 2 + 0];
                float v1 = acc[mf][nf][half * 2 + 1];
                if (!phase) {
                    *(float2*)(g_p1 + ((size_t)slice * HP + h) * DD + d) =
                        make_float2(v0, v1);
                }
                if (h < HO) {
                    *(float2*)(out + (((size_t)(nb * HO + h) * FB + f) * DD + d)) =
                        make_float2(tanhf(v0), tanhf(v1));
                }
            }
        }
    }
}

// ---------------------------------------------------------------------------
extern "C" void kernel_launch(void* const* d_in, const int* in_sizes, int n_in,
                              void* d_out, int out_size)
{
    const float* prot1 = (const float*)d_in[0];
    const float* prot2 = (const float*)d_in[1];
    const float* W     = (const float*)d_in[2];
    float* out = (float*)d_out;

    cudaFuncSetAttribute(att_kernel, cudaFuncAttributeMaxDynamicSharedMemorySize,
                         128 * 64 * 4 * 2);

    proj_kernel<<<dim3(32, FB, NB), 256>>>(prot1, W, 0);
    proj_kernel<<<dim3(32, FB, NB), 256>>>(prot2, W, 1);
    att_kernel<<<dim3(8, 8, NSLICE), 256, 128 * 64 * 4 * 2>>>();
    softmax_kernel<<<NSLICE * HP, 256>>>();
    pv_kernel<<<dim3(4, NSLICE), 256>>>(out, 0);
    pv_kernel<<<dim3(4, NSLICE), 256>>>(out + (size_t)NB * HO * FB * DD, 1);
}

// round 4
// speedup vs baseline: 2.4897x; 1.5467x over previous
#include <cuda_runtime.h>
#include <cuda_fp16.h>
#include <math.h>

#define NB 4
#define FB 32
#define HIN 1024
#define CIN 8
#define DD 64
#define WW 7
#define HO 1018
#define HP 1024
#define NSLICE (NB*FB)

// fp16 scratch (zero-initialized; padded rows never written -> stay 0)
__device__ __half g_q1h[(size_t)NSLICE * HP * DD];
__device__ __half g_q2h[(size_t)NSLICE * HP * DD];
__device__ __half g_p1h[(size_t)NSLICE * HP * DD];

// ---------------------------------------------------------------------------
// helpers
// ---------------------------------------------------------------------------
__device__ __forceinline__ void mma16(float* d, const unsigned* a, unsigned b0, unsigned b1) {
    asm volatile(
        "mma.sync.aligned.m16n8k16.row.col.f32.f16.f16.f32 "
        "{%0,%1,%2,%3},{%4,%5,%6,%7},{%8,%9},{%0,%1,%2,%3};"
        : "+f"(d[0]), "+f"(d[1]), "+f"(d[2]), "+f"(d[3])
        : "r"(a[0]), "r"(a[1]), "r"(a[2]), "r"(a[3]), "r"(b0), "r"(b1));
}

__device__ __forceinline__ void ldsm4(unsigned* r, const void* p) {
    unsigned a = (unsigned)__cvta_generic_to_shared(p);
    asm volatile("ldmatrix.sync.aligned.m8n8.x4.shared.b16 {%0,%1,%2,%3},[%4];"
                 : "=r"(r[0]), "=r"(r[1]), "=r"(r[2]), "=r"(r[3]) : "r"(a));
}

__device__ __forceinline__ void ldsm4t(unsigned* r, const void* p) {
    unsigned a = (unsigned)__cvta_generic_to_shared(p);
    asm volatile("ldmatrix.sync.aligned.m8n8.x4.trans.shared.b16 {%0,%1,%2,%3},[%4];"
                 : "=r"(r[0]), "=r"(r[1]), "=r"(r[2]), "=r"(r[3]) : "r"(a));
}

__device__ __forceinline__ void cpa16(void* s, const void* g) {
    unsigned sa = (unsigned)__cvta_generic_to_shared(s);
    asm volatile("cp.async.cg.shared.global [%0],[%1],16;" :: "r"(sa), "l"(g));
}
#define CP_COMMIT asm volatile("cp.async.commit_group;")
#define CP_WAIT0  asm volatile("cp.async.wait_group 0;")
#define CP_WAIT1  asm volatile("cp.async.wait_group 1;")

__device__ __forceinline__ unsigned h2u(float x, float y) {
    __half2 h = __float22half2_rn(make_float2(x, y));
    return *(unsigned*)&h;
}

// ---------------------------------------------------------------------------
// Projection: q[n,f,h,d] = sum_{c,j} x[n,h+j,c,d] * W[f,c,d,j]  -> fp16
// ---------------------------------------------------------------------------
__global__ __launch_bounds__(256) void proj_kernel(const float* __restrict__ x,
                                                   const float* __restrict__ W,
                                                   int which)
{
    __shared__ float Ws[CIN * DD * WW];
    const int f = blockIdx.y, n = blockIdx.z;
    const float* Wf = W + (size_t)f * CIN * DD * WW;
    for (int i = threadIdx.x; i < CIN * DD * WW; i += 256) Ws[i] = Wf[i];
    __syncthreads();

    __half* q = which ? g_q2h : g_q1h;
    const int h0 = blockIdx.x * 32;
#pragma unroll
    for (int r = 0; r < 8; r++) {
        int idx = threadIdx.x + r * 256;
        int hl = idx >> 6, d = idx & 63;
        int h = h0 + hl;
        if (h >= HO) continue;
        const float* xb = x + ((size_t)(n * HIN + h) * CIN) * DD + d;
        float acc = 0.f;
#pragma unroll
        for (int j = 0; j < WW; j++)
#pragma unroll
            for (int c = 0; c < CIN; c++)
                acc += xb[(j * CIN + c) * DD] * Ws[(c * DD + d) * WW + j];
        q[((size_t)(n * FB + f) * HP + h) * DD + d] = __float2half(acc);
    }
}

// ---------------------------------------------------------------------------
// Fused attention pass. CTA = 64 h-rows x full g (1024). 512 threads,
// 16 warps = 4 m-groups (16 rows) x 4 g-groups (256 cols each).
// phase 0: S=Q1*Q2^T, softmax, p1 = P*Q2/l  -> store p1(half) + tanh->out1
// phase 1: S=Q1*Q2^T (Q2 streamed), softmax, p2 = P*p1/l -> tanh->out2
// smem: Vs 1024x72 half (147456) | Q1s 64x72 (9216) | Ks 2x128x72 (36864)
//       | red 4x64 f32 | lsm 64 f32.  Obuf (4x64x64 f32) overlays Vs.
// ---------------------------------------------------------------------------
#define SMEM_FUSED 194816

__global__ __launch_bounds__(512, 1) void fused_kernel(float* __restrict__ out, int phase)
{
    extern __shared__ __align__(16) char sm[];
    __half* Vs  = (__half*)sm;
    __half* Q1s = (__half*)(sm + 147456);
    __half* Ks  = (__half*)(sm + 156672);
    float*  red = (float*)(sm + 193536);
    float*  lsm = (float*)(sm + 194560);
    float*  Obuf = (float*)sm;

    const int slice = blockIdx.y;
    const int h0 = blockIdx.x * 64;
    const int tid = threadIdx.x;
    const int warp = tid >> 5, lane = tid & 31;
    const int gw = warp & 3, mw = warp >> 2;
    const int gq = lane >> 2, qi = lane & 3;

    const __half* Vg  = (phase ? g_p1h : g_q2h) + (size_t)slice * HP * DD;
    const __half* Kg  = g_q2h + (size_t)slice * HP * DD;
    const __half* Q1g = g_q1h + ((size_t)slice * HP + h0) * DD;

    // resident V (1024x64 -> ld 72) + Q1 tile (64x64 -> ld 72)
#pragma unroll
    for (int r = 0; r < 16; r++) {
        int op = tid + r * 512, row = op >> 3, c = op & 7;
        cpa16(Vs + row * 72 + c * 8, Vg + row * 64 + c * 8);
    }
    { int row = tid >> 3, c = tid & 7;
      cpa16(Q1s + row * 72 + c * 8, Q1g + row * 64 + c * 8); }
    CP_COMMIT;
    if (phase) {   // prefetch K chunk 0
#pragma unroll
        for (int r = 0; r < 2; r++) {
            int op = tid + r * 512, row = op >> 3, c = op & 7;
            cpa16(Ks + row * 72 + c * 8, Kg + row * 64 + c * 8);
        }
        CP_COMMIT;
        CP_WAIT1;
    } else {
        CP_WAIT0;
    }
    __syncthreads();

    // A fragments: Q1 rows mw*16..+15, 4 k16 steps (regs reused all chunks)
    unsigned afr[4][4];
#pragma unroll
    for (int ks = 0; ks < 4; ks++)
        ldsm4(afr[ks], Q1s + (mw * 16 + (lane & 15)) * 72 + (lane >> 4) * 8 + ks * 16);

    // ---- S = Q1 * K^T : acc[j] = n-frag j; gcol(j) = (j/4)*128 + gw*32 + (j%4)*8
    float acc[32][4] = {};
    for (int c = 0; c < 8; c++) {
        const __half* Bb;
        if (phase) {
            CP_WAIT0;
            __syncthreads();
            if (c < 7) {
#pragma unroll
                for (int r = 0; r < 2; r++) {
                    int op = tid + r * 512, row = op >> 3, cc = op & 7;
                    cpa16(Ks + (((c + 1) & 1) * 128 + row) * 72 + cc * 8,
                          Kg + ((size_t)((c + 1) * 128 + row)) * 64 + cc * 8);
                }
                CP_COMMIT;
            }
            Bb = Ks + (c & 1) * 128 * 72;
        } else {
            Bb = Vs + c * 128 * 72;
        }
#pragma unroll
        for (int pf = 0; pf < 2; pf++) {
            int gloc = gw * 32 + pf * 16;
            unsigned b[4][4];
#pragma unroll
            for (int ks = 0; ks < 4; ks++)
                ldsm4(b[ks], Bb + (gloc + (lane & 15)) * 72 + (lane >> 4) * 8 + ks * 16);
            int j0 = c * 4 + pf * 2;
#pragma unroll
            for (int ks = 0; ks < 4; ks++) {
                mma16(acc[j0],     afr[ks], b[ks][0], b[ks][2]);
                mma16(acc[j0 + 1], afr[ks], b[ks][1], b[ks][3]);
            }
        }
    }

    // ---- exact softmax over the full row (in registers)
    const float sc = 1.0f / 1018.0f;
    float mx0 = -1e30f, mx1 = -1e30f;
#pragma unroll
    for (int j = 0; j < 32; j++) {
        mx0 = fmaxf(mx0, fmaxf(acc[j][0], acc[j][1]));
        mx1 = fmaxf(mx1, fmaxf(acc[j][2], acc[j][3]));
    }
#pragma unroll
    for (int o = 1; o <= 2; o <<= 1) {
        mx0 = fmaxf(mx0, __shfl_xor_sync(~0u, mx0, o));
        mx1 = fmaxf(mx1, __shfl_xor_sync(~0u, mx1, o));
    }
    if (qi == 0) {
        red[gw * 64 + mw * 16 + gq] = mx0;
        red[gw * 64 + mw * 16 + gq + 8] = mx1;
    }
    __syncthreads();
    float M0 = -1e30f, M1 = -1e30f;
#pragma unroll
    for (int g2 = 0; g2 < 4; g2++) {
        M0 = fmaxf(M0, red[g2 * 64 + mw * 16 + gq]);
        M1 = fmaxf(M1, red[g2 * 64 + mw * 16 + gq + 8]);
    }
    __syncthreads();

    float l0 = 0.f, l1 = 0.f;
#pragma unroll
    for (int j = 0; j < 32; j++) {
        int gcol = (j >> 2) * 128 + gw * 32 + (j & 3) * 8 + 2 * qi;
        float e0 = (gcol < HO)     ? __expf((acc[j][0] - M0) * sc) : 0.f;
        float e1 = (gcol + 1 < HO) ? __expf((acc[j][1] - M0) * sc) : 0.f;
        float e2 = (gcol < HO)     ? __expf((acc[j][2] - M1) * sc) : 0.f;
        float e3 = (gcol + 1 < HO) ? __expf((acc[j][3] - M1) * sc) : 0.f;
        acc[j][0] = e0; acc[j][1] = e1; acc[j][2] = e2; acc[j][3] = e3;
        l0 += e0 + e1; l1 += e2 + e3;
    }
#pragma unroll
    for (int o = 1; o <= 2; o <<= 1) {
        l0 += __shfl_xor_sync(~0u, l0, o);
        l1 += __shfl_xor_sync(~0u, l1, o);
    }
    if (qi == 0) {
        red[gw * 64 + mw * 16 + gq] = l0;
        red[gw * 64 + mw * 16 + gq + 8] = l1;
    }
    __syncthreads();
    if (gw == 0 && qi == 0) {
        float L0 = 0.f, L1 = 0.f;
#pragma unroll
        for (int g2 = 0; g2 < 4; g2++) {
            L0 += red[g2 * 64 + mw * 16 + gq];
            L1 += red[g2 * 64 + mw * 16 + gq + 8];
        }
        lsm[mw * 16 + gq] = L0;
        lsm[mw * 16 + gq + 8] = L1;
    }

    // ---- O = P * V (partial over this warp's 256 g-cols); P stays in regs
    float od[8][4] = {};
#pragma unroll
    for (int jp = 0; jp < 16; jp++) {
        int j = jp * 2;
        int grow = (j >> 2) * 128 + gw * 32 + (j & 3) * 8;  // k16 = V rows grow..+15
        unsigned a[4];
        a[0] = h2u(acc[j][0], acc[j][1]);
        a[1] = h2u(acc[j][2], acc[j][3]);
        a[2] = h2u(acc[j + 1][0], acc[j + 1][1]);
        a[3] = h2u(acc[j + 1][2], acc[j + 1][3]);
#pragma unroll
        for (int dv = 0; dv < 4; dv++) {
            unsigned b[4];
            ldsm4t(b, Vs + (grow + (lane & 15)) * 72 + (lane >> 4) * 8 + dv * 16);
            mma16(od[dv * 2],     a, b[0], b[1]);
            mma16(od[dv * 2 + 1], a, b[2], b[3]);
        }
    }

    // ---- cross-warp reduce over the 4 g-groups (Obuf overlays Vs), epilogue
    __syncthreads();
#pragma unroll
    for (int nf = 0; nf < 8; nf++) {
        int row = mw * 16 + gq, d = nf * 8 + 2 * qi;
        *(float2*)&Obuf[((gw * 64) + row) * 64 + d] = make_float2(od[nf][0], od[nf][1]);
        *(float2*)&Obuf[((gw * 64) + row + 8) * 64 + d] = make_float2(od[nf][2], od[nf][3]);
    }
    __syncthreads();
    {
        int row = tid >> 3, d0 = (tid & 7) * 8;
        float inv = 1.0f / lsm[row];
        int h = h0 + row;
        const int nb = slice >> 5, f = slice & 31;
#pragma unroll
        for (int dd = 0; dd < 8; dd++) {
            int d = d0 + dd;
            float v = Obuf[(0 * 64 + row) * 64 + d] + Obuf[(1 * 64 + row) * 64 + d]
                    + Obuf[(2 * 64 + row) * 64 + d] + Obuf[(3 * 64 + row) * 64 + d];
            v *= inv;
            if (!phase)
                g_p1h[((size_t)slice * HP + h) * DD + d] = __float2half(v);
            if (h < HO)
                out[((size_t)(nb * HO + h) * FB + f) * DD + d] = tanhf(v);
        }
    }
}

// ---------------------------------------------------------------------------
extern "C" void kernel_launch(void* const* d_in, const int* in_sizes, int n_in,
                              void* d_out, int out_size)
{
    const float* prot1 = (const float*)d_in[0];
    const float* prot2 = (const float*)d_in[1];
    const float* W     = (const float*)d_in[2];
    float* out = (float*)d_out;

    cudaFuncSetAttribute(fused_kernel, cudaFuncAttributeMaxDynamicSharedMemorySize,
                         SMEM_FUSED);

    proj_kernel<<<dim3(32, FB, NB), 256>>>(prot1, W, 0);
    proj_kernel<<<dim3(32, FB, NB), 256>>>(prot2, W, 1);
    fused_kernel<<<dim3(16, NSLICE), 512, SMEM_FUSED>>>(out, 0);
    fused_kernel<<<dim3(16, NSLICE), 512, SMEM_FUSED>>>(out + (size_t)NB * HO * FB * DD, 1);
}

// round 5
// speedup vs baseline: 2.5223x; 1.0131x over previous
#include <cuda_runtime.h>
#include <cuda_fp16.h>
#include <math.h>

#define NB 4
#define FB 32
#define HIN 1024
#define CIN 8
#define DD 64
#define WW 7
#define HO 1018
#define HP 1024
#define NSLICE (NB*FB)

// fp16 scratch (zero-initialized; padded rows of q1/q2 never written -> stay 0)
__device__ __half g_q1h[(size_t)NSLICE * HP * DD];
__device__ __half g_q2h[(size_t)NSLICE * HP * DD];
__device__ __half g_p1h[(size_t)NSLICE * HP * DD];

// ---------------------------------------------------------------------------
// helpers
// ---------------------------------------------------------------------------
__device__ __forceinline__ void mma16(float* d, const unsigned* a, unsigned b0, unsigned b1) {
    asm volatile(
        "mma.sync.aligned.m16n8k16.row.col.f32.f16.f16.f32 "
        "{%0,%1,%2,%3},{%4,%5,%6,%7},{%8,%9},{%0,%1,%2,%3};"
        : "+f"(d[0]), "+f"(d[1]), "+f"(d[2]), "+f"(d[3])
        : "r"(a[0]), "r"(a[1]), "r"(a[2]), "r"(a[3]), "r"(b0), "r"(b1));
}

__device__ __forceinline__ void ldsm4(unsigned* r, const void* p) {
    unsigned a = (unsigned)__cvta_generic_to_shared(p);
    asm volatile("ldmatrix.sync.aligned.m8n8.x4.shared.b16 {%0,%1,%2,%3},[%4];"
                 : "=r"(r[0]), "=r"(r[1]), "=r"(r[2]), "=r"(r[3]) : "r"(a));
}

__device__ __forceinline__ void ldsm4t(unsigned* r, const void* p) {
    unsigned a = (unsigned)__cvta_generic_to_shared(p);
    asm volatile("ldmatrix.sync.aligned.m8n8.x4.trans.shared.b16 {%0,%1,%2,%3},[%4];"
                 : "=r"(r[0]), "=r"(r[1]), "=r"(r[2]), "=r"(r[3]) : "r"(a));
}

__device__ __forceinline__ void cpa16(void* s, const void* g) {
    unsigned sa = (unsigned)__cvta_generic_to_shared(s);
    asm volatile("cp.async.cg.shared.global [%0],[%1],16;" :: "r"(sa), "l"(g));
}
#define CP_COMMIT asm volatile("cp.async.commit_group;")
#define CP_WAIT0  asm volatile("cp.async.wait_group 0;")
#define CP_WAIT1  asm volatile("cp.async.wait_group 1;")

__device__ __forceinline__ unsigned h2u(float x, float y) {
    __half2 h = __float22half2_rn(make_float2(x, y));
    return *(unsigned*)&h;
}

// ---------------------------------------------------------------------------
// Projection (both inputs in one launch): q[n,f,h,d] = sum_{c,j} x[n,h+j,c,d]*W[f,c,d,j]
// grid (32, F, 2N), z = n*2 + which
// ---------------------------------------------------------------------------
__global__ __launch_bounds__(256) void proj_kernel(const float* __restrict__ x1,
                                                   const float* __restrict__ x2,
                                                   const float* __restrict__ W)
{
    __shared__ float Ws[CIN * DD * WW];
    const int f = blockIdx.y;
    const int which = blockIdx.z & 1, n = blockIdx.z >> 1;
    const float* Wf = W + (size_t)f * CIN * DD * WW;
    for (int i = threadIdx.x; i < CIN * DD * WW; i += 256) Ws[i] = Wf[i];
    __syncthreads();

    const float* x = which ? x2 : x1;
    __half* q = which ? g_q2h : g_q1h;
    const int h0 = blockIdx.x * 32;
#pragma unroll
    for (int r = 0; r < 8; r++) {
        int idx = threadIdx.x + r * 256;
        int hl = idx >> 6, d = idx & 63;
        int h = h0 + hl;
        if (h >= HO) continue;
        const float* xb = x + ((size_t)(n * HIN + h) * CIN) * DD + d;
        float acc = 0.f;
#pragma unroll
        for (int j = 0; j < WW; j++)
#pragma unroll
            for (int c = 0; c < CIN; c++)
                acc += xb[(j * CIN + c) * DD] * Ws[(c * DD + d) * WW + j];
        q[((size_t)(n * FB + f) * HP + h) * DD + d] = __float2half(acc);
    }
}

// ---------------------------------------------------------------------------
// Fused attention pass. CTA = 32 h-rows x full g (1024). 512 threads,
// 16 warps = 2 m-groups (16 rows) x 8 g-groups (16 cols of each 128-chunk).
// phase 0: S=Q1*Q2^T, exact softmax, p1 = P*Q2/l -> store p1(half)+tanh->out1
// phase 1: S=Q1*Q2^T (Q2 streamed), softmax, p2 = P*p1/l -> tanh->out2
// smem: Vs 1024x72 half | Q1s 32x72 | Ks 2x128x72 | red 8x32 f32 | lsm 32 f32
//       Obuf (8x32x64 f32) overlays Vs after O-GEMM.
// ---------------------------------------------------------------------------
#define SM_Q1  147456
#define SM_KS  152064
#define SM_RED 188928
#define SM_LSM 189952
#define SMEM_FUSED 190080

__global__ __launch_bounds__(512, 1) void fused_kernel(float* __restrict__ out, int phase)
{
    extern __shared__ __align__(16) char sm[];
    __half* Vs  = (__half*)sm;
    __half* Q1s = (__half*)(sm + SM_Q1);
    __half* Ks  = (__half*)(sm + SM_KS);
    float*  red = (float*)(sm + SM_RED);
    float*  lsm = (float*)(sm + SM_LSM);
    float*  Obuf = (float*)sm;

    const int slice = blockIdx.y;
    const int h0 = blockIdx.x * 32;
    const int tid = threadIdx.x;
    const int warp = tid >> 5, lane = tid & 31;
    const int gw = warp & 7, mw = warp >> 3;      // 8 g-groups x 2 m-groups
    const int gq = lane >> 2, qi = lane & 3;

    const __half* Vg  = (phase ? g_p1h : g_q2h) + (size_t)slice * HP * DD;
    const __half* Kg  = g_q2h + (size_t)slice * HP * DD;
    const __half* Q1g = g_q1h + ((size_t)slice * HP + h0) * DD;

    // resident V (1024x64 -> ld 72) + Q1 tile (32x64 -> ld 72)
#pragma unroll
    for (int r = 0; r < 16; r++) {
        int op = tid + r * 512, row = op >> 3, c = op & 7;
        cpa16(Vs + row * 72 + c * 8, Vg + row * 64 + c * 8);
    }
    if (tid < 256) {
        int row = tid >> 3, c = tid & 7;
        cpa16(Q1s + row * 72 + c * 8, Q1g + row * 64 + c * 8);
    }
    CP_COMMIT;
    if (phase) {   // prefetch K chunk 0
#pragma unroll
        for (int r = 0; r < 2; r++) {
            int op = tid + r * 512, row = op >> 3, c = op & 7;
            cpa16(Ks + row * 72 + c * 8, Kg + row * 64 + c * 8);
        }
        CP_COMMIT;
        CP_WAIT1;
    } else {
        CP_WAIT0;
    }
    __syncthreads();

    // A fragments: Q1 rows mw*16..+15, 4 k16 steps
    unsigned afr[4][4];
#pragma unroll
    for (int ks = 0; ks < 4; ks++)
        ldsm4(afr[ks], Q1s + (mw * 16 + (lane & 15)) * 72 + (lane >> 4) * 8 + ks * 16);

    // ---- S = Q1*K^T. Warp's cols: {c*128 + gw*16 + 0..15}, j = c*2 + half
    float acc[16][4] = {};
    for (int c = 0; c < 8; c++) {
        const __half* Bb;
        if (phase) {
            CP_WAIT0;
            __syncthreads();
            if (c < 7) {
#pragma unroll
                for (int r = 0; r < 2; r++) {
                    int op = tid + r * 512, row = op >> 3, cc = op & 7;
                    cpa16(Ks + (((c + 1) & 1) * 128 + row) * 72 + cc * 8,
                          Kg + ((size_t)((c + 1) * 128 + row)) * 64 + cc * 8);
                }
                CP_COMMIT;
            }
            Bb = Ks + (c & 1) * 128 * 72;
        } else {
            Bb = Vs + c * 128 * 72;
        }
        unsigned b[4][4];
#pragma unroll
        for (int ks = 0; ks < 4; ks++)
            ldsm4(b[ks], Bb + (gw * 16 + (lane & 15)) * 72 + (lane >> 4) * 8 + ks * 16);
#pragma unroll
        for (int ks = 0; ks < 4; ks++) {
            mma16(acc[c * 2],     afr[ks], b[ks][0], b[ks][2]);
            mma16(acc[c * 2 + 1], afr[ks], b[ks][1], b[ks][3]);
        }
    }

    // ---- exact softmax over full row (registers + smem cross-warp reduce)
    const float sc = 1.0f / 1018.0f;
    float mx0 = -1e30f, mx1 = -1e30f;
#pragma unroll
    for (int j = 0; j < 16; j++) {
        mx0 = fmaxf(mx0, fmaxf(acc[j][0], acc[j][1]));
        mx1 = fmaxf(mx1, fmaxf(acc[j][2], acc[j][3]));
    }
#pragma unroll
    for (int o = 1; o <= 2; o <<= 1) {
        mx0 = fmaxf(mx0, __shfl_xor_sync(~0u, mx0, o));
        mx1 = fmaxf(mx1, __shfl_xor_sync(~0u, mx1, o));
    }
    if (qi == 0) {
        red[gw * 32 + mw * 16 + gq] = mx0;
        red[gw * 32 + mw * 16 + gq + 8] = mx1;
    }
    __syncthreads();
    float M0 = -1e30f, M1 = -1e30f;
#pragma unroll
    for (int g2 = 0; g2 < 8; g2++) {
        M0 = fmaxf(M0, red[g2 * 32 + mw * 16 + gq]);
        M1 = fmaxf(M1, red[g2 * 32 + mw * 16 + gq + 8]);
    }
    __syncthreads();

    float l0 = 0.f, l1 = 0.f;
#pragma unroll
    for (int j = 0; j < 16; j++) {
        int gcol = (j >> 1) * 128 + gw * 16 + (j & 1) * 8 + 2 * qi;
        float e0 = (gcol < HO)     ? __expf((acc[j][0] - M0) * sc) : 0.f;
        float e1 = (gcol + 1 < HO) ? __expf((acc[j][1] - M0) * sc) : 0.f;
        float e2 = (gcol < HO)     ? __expf((acc[j][2] - M1) * sc) : 0.f;
        float e3 = (gcol + 1 < HO) ? __expf((acc[j][3] - M1) * sc) : 0.f;
        acc[j][0] = e0; acc[j][1] = e1; acc[j][2] = e2; acc[j][3] = e3;
        l0 += e0 + e1; l1 += e2 + e3;
    }
#pragma unroll
    for (int o = 1; o <= 2; o <<= 1) {
        l0 += __shfl_xor_sync(~0u, l0, o);
        l1 += __shfl_xor_sync(~0u, l1, o);
    }
    if (qi == 0) {
        red[gw * 32 + mw * 16 + gq] = l0;
        red[gw * 32 + mw * 16 + gq + 8] = l1;
    }
    __syncthreads();
    if (gw == 0 && qi == 0) {
        float L0 = 0.f, L1 = 0.f;
#pragma unroll
        for (int g2 = 0; g2 < 8; g2++) {
            L0 += red[g2 * 32 + mw * 16 + gq];
            L1 += red[g2 * 32 + mw * 16 + gq + 8];
        }
        lsm[mw * 16 + gq] = L0;
        lsm[mw * 16 + gq + 8] = L1;
    }

    // ---- O = P*V partial over this warp's 128 g-cols; P stays in registers
    float od[8][4] = {};
#pragma unroll
    for (int c = 0; c < 8; c++) {
        int grow = c * 128 + gw * 16;            // k16 = V rows grow..grow+15
        unsigned a[4];
        a[0] = h2u(acc[c * 2][0],     acc[c * 2][1]);
        a[1] = h2u(acc[c * 2][2],     acc[c * 2][3]);
        a[2] = h2u(acc[c * 2 + 1][0], acc[c * 2 + 1][1]);
        a[3] = h2u(acc[c * 2 + 1][2], acc[c * 2 + 1][3]);
#pragma unroll
        for (int dv = 0; dv < 4; dv++) {
            unsigned b[4];
            ldsm4t(b, Vs + (grow + (lane & 15)) * 72 + (lane >> 4) * 8 + dv * 16);
            mma16(od[dv * 2],     a, b[0], b[1]);
            mma16(od[dv * 2 + 1], a, b[2], b[3]);
        }
    }

    // ---- cross-warp reduce over the 8 g-groups (Obuf overlays Vs), epilogue
    __syncthreads();
#pragma unroll
    for (int nf = 0; nf < 8; nf++) {
        int row = mw * 16 + gq, d = nf * 8 + 2 * qi;
        *(float2*)&Obuf[(gw * 32 + row) * 64 + d] = make_float2(od[nf][0], od[nf][1]);
        *(float2*)&Obuf[(gw * 32 + row + 8) * 64 + d] = make_float2(od[nf][2], od[nf][3]);
    }
    __syncthreads();
    {
        int row = tid >> 4, d0 = (tid & 15) * 4;
        float inv = 1.0f / lsm[row];
        int h = h0 + row;
        const int nb = slice >> 5, f = slice & 31;
#pragma unroll
        for (int dd = 0; dd < 4; dd++) {
            int d = d0 + dd;
            float v = 0.f;
#pragma unroll
            for (int g2 = 0; g2 < 8; g2++) v += Obuf[(g2 * 32 + row) * 64 + d];
            v *= inv;
            if (!phase)
                g_p1h[((size_t)slice * HP + h) * DD + d] = __float2half(v);
            if (h < HO)
                out[((size_t)(nb * HO + h) * FB + f) * DD + d] = tanhf(v);
        }
    }
}

// ---------------------------------------------------------------------------
extern "C" void kernel_launch(void* const* d_in, const int* in_sizes, int n_in,
                              void* d_out, int out_size)
{
    const float* prot1 = (const float*)d_in[0];
    const float* prot2 = (const float*)d_in[1];
    const float* W     = (const float*)d_in[2];
    float* out = (float*)d_out;

    cudaFuncSetAttribute(fused_kernel, cudaFuncAttributeMaxDynamicSharedMemorySize,
                         SMEM_FUSED);

    proj_kernel<<<dim3(32, FB, 2 * NB), 256>>>(prot1, prot2, W);
    fused_kernel<<<dim3(32, NSLICE), 512, SMEM_FUSED>>>(out, 0);
    fused_kernel<<<dim3(32, NSLICE), 512, SMEM_FUSED>>>(out + (size_t)NB * HO * FB * DD, 1);
}

// round 7
// speedup vs baseline: 2.9794x; 1.1812x over previous
#include <cuda_runtime.h>
#include <cuda_fp16.h>
#include <math.h>

#define NB 4
#define FB 32
#define HIN 1024
#define CIN 8
#define DD 64
#define WW 7
#define HO 1018
#define HP 1024
#define NSLICE (NB*FB)

// fp16 scratch (zero-initialized; padded rows of q1/q2 never written -> stay 0)
__device__ __half g_q1h[(size_t)NSLICE * HP * DD];
__device__ __half g_q2h[(size_t)NSLICE * HP * DD];
__device__ __half g_p1h[(size_t)NSLICE * HP * DD];

// ---------------------------------------------------------------------------
// helpers
// ---------------------------------------------------------------------------
__device__ __forceinline__ void mma16(float* d, const unsigned* a, unsigned b0, unsigned b1) {
    asm volatile(
        "mma.sync.aligned.m16n8k16.row.col.f32.f16.f16.f32 "
        "{%0,%1,%2,%3},{%4,%5,%6,%7},{%8,%9},{%0,%1,%2,%3};"
        : "+f"(d[0]), "+f"(d[1]), "+f"(d[2]), "+f"(d[3])
        : "r"(a[0]), "r"(a[1]), "r"(a[2]), "r"(a[3]), "r"(b0), "r"(b1));
}

__device__ __forceinline__ void ldsm4(unsigned* r, const void* p) {
    unsigned a = (unsigned)__cvta_generic_to_shared(p);
    asm volatile("ldmatrix.sync.aligned.m8n8.x4.shared.b16 {%0,%1,%2,%3},[%4];"
                 : "=r"(r[0]), "=r"(r[1]), "=r"(r[2]), "=r"(r[3]) : "r"(a));
}

__device__ __forceinline__ void ldsm4t(unsigned* r, const void* p) {
    unsigned a = (unsigned)__cvta_generic_to_shared(p);
    asm volatile("ldmatrix.sync.aligned.m8n8.x4.trans.shared.b16 {%0,%1,%2,%3},[%4];"
                 : "=r"(r[0]), "=r"(r[1]), "=r"(r[2]), "=r"(r[3]) : "r"(a));
}

__device__ __forceinline__ void cpa16(void* s, const void* g) {
    unsigned sa = (unsigned)__cvta_generic_to_shared(s);
    asm volatile("cp.async.cg.shared.global [%0],[%1],16;" :: "r"(sa), "l"(g));
}
#define CP_COMMIT asm volatile("cp.async.commit_group;")
#define CP_WAIT0  asm volatile("cp.async.wait_group 0;")
#define CP_WAIT1  asm volatile("cp.async.wait_group 1;")

__device__ __forceinline__ unsigned h2u(float x, float y) {
    __half2 h = __float22half2_rn(make_float2(x, y));
    return *(unsigned*)&h;
}

// ---------------------------------------------------------------------------
// Projection, register-blocked sliding window.
// Thread = (h-block of 16 rows) x (d-pair). CTA 256 thr = 8 hblk x 32 dpair
// -> covers 128 h rows for one (f, n, which). grid (8, F, 2N).
// Per thread: 8 channels x 22-row window in regs, 7 taps from regs.
// ---------------------------------------------------------------------------
__global__ __launch_bounds__(256) void proj_kernel(const float* __restrict__ x1,
                                                   const float* __restrict__ x2,
                                                   const float* __restrict__ W)
{
    __shared__ float Ws[CIN * DD * WW];
    const int f = blockIdx.y;
    const int which = blockIdx.z & 1, n = blockIdx.z >> 1;
    const float* Wf = W + (size_t)f * CIN * DD * WW;
    for (int i = threadIdx.x; i < CIN * DD * WW; i += 256) Ws[i] = Wf[i];
    __syncthreads();

    const float* x = which ? x2 : x1;
    __half* q = which ? g_q2h : g_q1h;

    const int tid = threadIdx.x;
    const int d = (tid & 31) * 2;
    const int hb = tid >> 5;
    const int h0 = blockIdx.x * 128 + hb * 16;

    float2 acc[16];
#pragma unroll
    for (int i = 0; i < 16; i++) acc[i] = make_float2(0.f, 0.f);

#pragma unroll
    for (int c = 0; c < CIN; c++) {
        float2 xc[22];
#pragma unroll
        for (int i = 0; i < 22; i++) {
            int hr = h0 + i;
            hr = hr < HIN ? hr : HIN - 1;   // clamp (outputs there are discarded)
            xc[i] = *(const float2*)(x + ((size_t)(n * HIN + hr) * CIN + c) * DD + d);
        }
#pragma unroll
        for (int j = 0; j < WW; j++) {
            float w0 = Ws[(c * DD + d) * WW + j];
            float w1 = Ws[(c * DD + d + 1) * WW + j];
#pragma unroll
            for (int i = 0; i < 16; i++) {
                acc[i].x += xc[i + j].x * w0;
                acc[i].y += xc[i + j].y * w1;
            }
        }
    }

    __half* qb = q + ((size_t)(n * FB + f) * HP) * DD + d;
#pragma unroll
    for (int i = 0; i < 16; i++) {
        int h = h0 + i;
        if (h < HO)
            *(__half2*)(qb + (size_t)h * DD) = __floats2half2_rn(acc[i].x, acc[i].y);
    }
}

// ---------------------------------------------------------------------------
// Fused attention pass (unchanged from round 5). CTA = 32 h-rows x full g.
// 512 threads, 16 warps = 2 m-groups (16 rows) x 8 g-groups.
// ---------------------------------------------------------------------------
#define SM_Q1  147456
#define SM_KS  152064
#define SM_RED 188928
#define SM_LSM 189952
#define SMEM_FUSED 190080

__global__ __launch_bounds__(512, 1) void fused_kernel(float* __restrict__ out, int phase)
{
    extern __shared__ __align__(16) char sm[];
    __half* Vs  = (__half*)sm;
    __half* Q1s = (__half*)(sm + SM_Q1);
    __half* Ks  = (__half*)(sm + SM_KS);
    float*  red = (float*)(sm + SM_RED);
    float*  lsm = (float*)(sm + SM_LSM);
    float*  Obuf = (float*)sm;

    const int slice = blockIdx.y;
    const int h0 = blockIdx.x * 32;
    const int tid = threadIdx.x;
    const int warp = tid >> 5, lane = tid & 31;
    const int gw = warp & 7, mw = warp >> 3;
    const int gq = lane >> 2, qi = lane & 3;

    const __half* Vg  = (phase ? g_p1h : g_q2h) + (size_t)slice * HP * DD;
    const __half* Kg  = g_q2h + (size_t)slice * HP * DD;
    const __half* Q1g = g_q1h + ((size_t)slice * HP + h0) * DD;

#pragma unroll
    for (int r = 0; r < 16; r++) {
        int op = tid + r * 512, row = op >> 3, c = op & 7;
        cpa16(Vs + row * 72 + c * 8, Vg + row * 64 + c * 8);
    }
    if (tid < 256) {
        int row = tid >> 3, c = tid & 7;
        cpa16(Q1s + row * 72 + c * 8, Q1g + row * 64 + c * 8);
    }
    CP_COMMIT;
    if (phase) {
#pragma unroll
        for (int r = 0; r < 2; r++) {
            int op = tid + r * 512, row = op >> 3, c = op & 7;
            cpa16(Ks + row * 72 + c * 8, Kg + row * 64 + c * 8);
        }
        CP_COMMIT;
        CP_WAIT1;
    } else {
        CP_WAIT0;
    }
    __syncthreads();

    unsigned afr[4][4];
#pragma unroll
    for (int ks = 0; ks < 4; ks++)
        ldsm4(afr[ks], Q1s + (mw * 16 + (lane & 15)) * 72 + (lane >> 4) * 8 + ks * 16);

    float acc[16][4] = {};
    for (int c = 0; c < 8; c++) {
        const __half* Bb;
        if (phase) {
            CP_WAIT0;
            __syncthreads();
            if (c < 7) {
#pragma unroll
                for (int r = 0; r < 2; r++) {
                    int op = tid + r * 512, row = op >> 3, cc = op & 7;
                    cpa16(Ks + (((c + 1) & 1) * 128 + row) * 72 + cc * 8,
                          Kg + ((size_t)((c + 1) * 128 + row)) * 64 + cc * 8);
                }
                CP_COMMIT;
            }
            Bb = Ks + (c & 1) * 128 * 72;
        } else {
            Bb = Vs + c * 128 * 72;
        }
        unsigned b[4][4];
#pragma unroll
        for (int ks = 0; ks < 4; ks++)
            ldsm4(b[ks], Bb + (gw * 16 + (lane & 15)) * 72 + (lane >> 4) * 8 + ks * 16);
#pragma unroll
        for (int ks = 0; ks < 4; ks++) {
            mma16(acc[c * 2],     afr[ks], b[ks][0], b[ks][2]);
            mma16(acc[c * 2 + 1], afr[ks], b[ks][1], b[ks][3]);
        }
    }

    const float sc = 1.0f / 1018.0f;
    float mx0 = -1e30f, mx1 = -1e30f;
#pragma unroll
    for (int j = 0; j < 16; j++) {
        mx0 = fmaxf(mx0, fmaxf(acc[j][0], acc[j][1]));
        mx1 = fmaxf(mx1, fmaxf(acc[j][2], acc[j][3]));
    }
#pragma unroll
    for (int o = 1; o <= 2; o <<= 1) {
        mx0 = fmaxf(mx0, __shfl_xor_sync(~0u, mx0, o));
        mx1 = fmaxf(mx1, __shfl_xor_sync(~0u, mx1, o));
    }
    if (qi == 0) {
        red[gw * 32 + mw * 16 + gq] = mx0;
        red[gw * 32 + mw * 16 + gq + 8] = mx1;
    }
    __syncthreads();
    float M0 = -1e30f, M1 = -1e30f;
#pragma unroll
    for (int g2 = 0; g2 < 8; g2++) {
        M0 = fmaxf(M0, red[g2 * 32 + mw * 16 + gq]);
        M1 = fmaxf(M1, red[g2 * 32 + mw * 16 + gq + 8]);
    }
    __syncthreads();

    float l0 = 0.f, l1 = 0.f;
#pragma unroll
    for (int j = 0; j < 16; j++) {
        int gcol = (j >> 1) * 128 + gw * 16 + (j & 1) * 8 + 2 * qi;
        float e0 = (gcol < HO)     ? __expf((acc[j][0] - M0) * sc) : 0.f;
        float e1 = (gcol + 1 < HO) ? __expf((acc[j][1] - M0) * sc) : 0.f;
        float e2 = (gcol < HO)     ? __expf((acc[j][2] - M1) * sc) : 0.f;
        float e3 = (gcol + 1 < HO) ? __expf((acc[j][3] - M1) * sc) : 0.f;
        acc[j][0] = e0; acc[j][1] = e1; acc[j][2] = e2; acc[j][3] = e3;
        l0 += e0 + e1; l1 += e2 + e3;
    }
#pragma unroll
    for (int o = 1; o <= 2; o <<= 1) {
        l0 += __shfl_xor_sync(~0u, l0, o);
        l1 += __shfl_xor_sync(~0u, l1, o);
    }
    if (qi == 0) {
        red[gw * 32 + mw * 16 + gq] = l0;
        red[gw * 32 + mw * 16 + gq + 8] = l1;
    }
    __syncthreads();
    if (gw == 0 && qi == 0) {
        float L0 = 0.f, L1 = 0.f;
#pragma unroll
        for (int g2 = 0; g2 < 8; g2++) {
            L0 += red[g2 * 32 + mw * 16 + gq];
            L1 += red[g2 * 32 + mw * 16 + gq + 8];
        }
        lsm[mw * 16 + gq] = L0;
        lsm[mw * 16 + gq + 8] = L1;
    }

    float od[8][4] = {};
#pragma unroll
    for (int c = 0; c < 8; c++) {
        int grow = c * 128 + gw * 16;
        unsigned a[4];
        a[0] = h2u(acc[c * 2][0],     acc[c * 2][1]);
        a[1] = h2u(acc[c * 2][2],     acc[c * 2][3]);
        a[2] = h2u(acc[c * 2 + 1][0], acc[c * 2 + 1][1]);
        a[3] = h2u(acc[c * 2 + 1][2], acc[c * 2 + 1][3]);
#pragma unroll
        for (int dv = 0; dv < 4; dv++) {
            unsigned b[4];
            ldsm4t(b, Vs + (grow + (lane & 15)) * 72 + (lane >> 4) * 8 + dv * 16);
            mma16(od[dv * 2],     a, b[0], b[1]);
            mma16(od[dv * 2 + 1], a, b[2], b[3]);
        }
    }

    __syncthreads();
#pragma unroll
    for (int nf = 0; nf < 8; nf++) {
        int row = mw * 16 + gq, d = nf * 8 + 2 * qi;
        *(float2*)&Obuf[(gw * 32 + row) * 64 + d] = make_float2(od[nf][0], od[nf][1]);
        *(float2*)&Obuf[(gw * 32 + row + 8) * 64 + d] = make_float2(od[nf][2], od[nf][3]);
    }
    __syncthreads();
    {
        int row = tid >> 4, d0 = (tid & 15) * 4;
        float inv = 1.0f / lsm[row];
        int h = h0 + row;
        const int nb = slice >> 5, f = slice & 31;
#pragma unroll
        for (int dd = 0; dd < 4; dd++) {
            int d = d0 + dd;
            float v = 0.f;
#pragma unroll
            for (int g2 = 0; g2 < 8; g2++) v += Obuf[(g2 * 32 + row) * 64 + d];
            v *= inv;
            if (!phase)
                g_p1h[((size_t)slice * HP + h) * DD + d] = __float2half(v);
            if (h < HO)
                out[((size_t)(nb * HO + h) * FB + f) * DD + d] = tanhf(v);
        }
    }
}

// ---------------------------------------------------------------------------
extern "C" void kernel_launch(void* const* d_in, const int* in_sizes, int n_in,
                              void* d_out, int out_size)
{
    const float* prot1 = (const float*)d_in[0];
    const float* prot2 = (const float*)d_in[1];
    const float* W     = (const float*)d_in[2];
    float* out = (float*)d_out;

    cudaFuncSetAttribute(fused_kernel, cudaFuncAttributeMaxDynamicSharedMemorySize,
                         SMEM_FUSED);

    proj_kernel<<<dim3(8, FB, 2 * NB), 256>>>(prot1, prot2, W);
    fused_kernel<<<dim3(32, NSLICE), 512, SMEM_FUSED>>>(out, 0);
    fused_kernel<<<dim3(32, NSLICE), 512, SMEM_FUSED>>>(out + (size_t)NB * HO * FB * DD, 1);
}

// round 8
// speedup vs baseline: 3.3354x; 1.1195x over previous
#include <cuda_runtime.h>
#include <cuda_fp16.h>
#include <math.h>

#define NB 4
#define FB 32
#define HIN 1024
#define CIN 8
#define DD 64
#define WW 7
#define HO 1018
#define HP 1024
#define NSLICE (NB*FB)

// fp16 scratch (zero-initialized; padded rows of q1/q2 never written -> stay 0)
__device__ __half g_q1h[(size_t)NSLICE * HP * DD];
__device__ __half g_q2h[(size_t)NSLICE * HP * DD];
__device__ __half g_p1h[(size_t)NSLICE * HP * DD];

// ---------------------------------------------------------------------------
// helpers
// ---------------------------------------------------------------------------
__device__ __forceinline__ void mma16(float* d, const unsigned* a, unsigned b0, unsigned b1) {
    asm volatile(
        "mma.sync.aligned.m16n8k16.row.col.f32.f16.f16.f32 "
        "{%0,%1,%2,%3},{%4,%5,%6,%7},{%8,%9},{%0,%1,%2,%3};"
        : "+f"(d[0]), "+f"(d[1]), "+f"(d[2]), "+f"(d[3])
        : "r"(a[0]), "r"(a[1]), "r"(a[2]), "r"(a[3]), "r"(b0), "r"(b1));
}

__device__ __forceinline__ void ldsm4(unsigned* r, const void* p) {
    unsigned a = (unsigned)__cvta_generic_to_shared(p);
    asm volatile("ldmatrix.sync.aligned.m8n8.x4.shared.b16 {%0,%1,%2,%3},[%4];"
                 : "=r"(r[0]), "=r"(r[1]), "=r"(r[2]), "=r"(r[3]) : "r"(a));
}

__device__ __forceinline__ void ldsm4t(unsigned* r, const void* p) {
    unsigned a = (unsigned)__cvta_generic_to_shared(p);
    asm volatile("ldmatrix.sync.aligned.m8n8.x4.trans.shared.b16 {%0,%1,%2,%3},[%4];"
                 : "=r"(r[0]), "=r"(r[1]), "=r"(r[2]), "=r"(r[3]) : "r"(a));
}

__device__ __forceinline__ void cpa16(void* s, const void* g) {
    unsigned sa = (unsigned)__cvta_generic_to_shared(s);
    asm volatile("cp.async.cg.shared.global [%0],[%1],16;" :: "r"(sa), "l"(g));
}
#define CP_COMMIT asm volatile("cp.async.commit_group;")
#define CP_WAIT0  asm volatile("cp.async.wait_group 0;")

__device__ __forceinline__ void cp_wait_dyn(int n) {
    switch (n) {
        case 0: asm volatile("cp.async.wait_group 0;"); break;
        case 1: asm volatile("cp.async.wait_group 1;"); break;
        case 2: asm volatile("cp.async.wait_group 2;"); break;
        case 3: asm volatile("cp.async.wait_group 3;"); break;
        case 4: asm volatile("cp.async.wait_group 4;"); break;
        case 5: asm volatile("cp.async.wait_group 5;"); break;
        case 6: asm volatile("cp.async.wait_group 6;"); break;
        default: asm volatile("cp.async.wait_group 7;"); break;
    }
}

__device__ __forceinline__ unsigned h2u(float x, float y) {
    __half2 h = __float22half2_rn(make_float2(x, y));
    return *(unsigned*)&h;
}

// ---------------------------------------------------------------------------
// Projection, register-blocked sliding window, 8 h-rows per thread.
// CTA 256 thr = 8 hblk x 32 dpair -> 64 h rows of one (f,n,which).
// grid (16, F, 2N).
// ---------------------------------------------------------------------------
__global__ __launch_bounds__(256) void proj_kernel(const float* __restrict__ x1,
                                                   const float* __restrict__ x2,
                                                   const float* __restrict__ W)
{
    __shared__ float Ws[CIN * DD * WW];
    const int f = blockIdx.y;
    const int which = blockIdx.z & 1, n = blockIdx.z >> 1;
    const float* Wf = W + (size_t)f * CIN * DD * WW;
    for (int i = threadIdx.x; i < CIN * DD * WW; i += 256) Ws[i] = Wf[i];
    __syncthreads();

    const float* x = which ? x2 : x1;
    __half* q = which ? g_q2h : g_q1h;

    const int tid = threadIdx.x;
    const int d = (tid & 31) * 2;
    const int hb = tid >> 5;
    const int h0 = blockIdx.x * 64 + hb * 8;

    float2 acc[8];
#pragma unroll
    for (int i = 0; i < 8; i++) acc[i] = make_float2(0.f, 0.f);

#pragma unroll
    for (int c = 0; c < CIN; c++) {
        float2 xc[14];
#pragma unroll
        for (int i = 0; i < 14; i++) {
            int hr = h0 + i;
            hr = hr < HIN ? hr : HIN - 1;   // clamp (those outputs are discarded)
            xc[i] = *(const float2*)(x + ((size_t)(n * HIN + hr) * CIN + c) * DD + d);
        }
#pragma unroll
        for (int j = 0; j < WW; j++) {
            float w0 = Ws[(c * DD + d) * WW + j];
            float w1 = Ws[(c * DD + d + 1) * WW + j];
#pragma unroll
            for (int i = 0; i < 8; i++) {
                acc[i].x += xc[i + j].x * w0;
                acc[i].y += xc[i + j].y * w1;
            }
        }
    }

    __half* qb = q + ((size_t)(n * FB + f) * HP) * DD + d;
#pragma unroll
    for (int i = 0; i < 8; i++) {
        int h = h0 + i;
        if (h < HO)
            *(__half2*)(qb + (size_t)h * DD) = __floats2half2_rn(acc[i].x, acc[i].y);
    }
}

// ---------------------------------------------------------------------------
// Fused attention pass. CTA = 32 h-rows x full g (1024). 512 threads,
// 16 warps = 2 m-groups (16 rows) x 8 g-groups (16 cols of each 128-chunk).
// V streamed in as 8 per-chunk cp.async groups; S-GEMM starts on chunk 0.
// No max-subtraction in softmax (args bounded; see analysis).
// ---------------------------------------------------------------------------
#define SM_Q1  147456
#define SM_KS  152064
#define SM_RED 188928
#define SM_LSM 189952
#define SMEM_FUSED 190080

__global__ __launch_bounds__(512, 1) void fused_kernel(float* __restrict__ out, int phase)
{
    extern __shared__ __align__(16) char sm[];
    __half* Vs  = (__half*)sm;
    __half* Q1s = (__half*)(sm + SM_Q1);
    __half* Ks  = (__half*)(sm + SM_KS);
    float*  red = (float*)(sm + SM_RED);
    float*  lsm = (float*)(sm + SM_LSM);
    float*  Obuf = (float*)sm;

    const int slice = blockIdx.y;
    const int h0 = blockIdx.x * 32;
    const int tid = threadIdx.x;
    const int warp = tid >> 5, lane = tid & 31;
    const int gw = warp & 7, mw = warp >> 3;
    const int gq = lane >> 2, qi = lane & 3;

    const __half* Vg  = (phase ? g_p1h : g_q2h) + (size_t)slice * HP * DD;
    const __half* Kg  = g_q2h + (size_t)slice * HP * DD;
    const __half* Q1g = g_q1h + ((size_t)slice * HP + h0) * DD;

    if (!phase) {
        // G0: Q1 tile; G1..G8: V chunks (also the K source in phase 0)
        if (tid < 256) {
            int row = tid >> 3, c8 = tid & 7;
            cpa16(Q1s + row * 72 + c8 * 8, Q1g + row * 64 + c8 * 8);
        }
        CP_COMMIT;
        for (int c = 0; c < 8; c++) {
#pragma unroll
            for (int r = 0; r < 2; r++) {
                int op = tid + r * 512, row = op >> 3, cc = op & 7;
                cpa16(Vs + (c * 128 + row) * 72 + cc * 8,
                      Vg + ((size_t)(c * 128 + row)) * 64 + cc * 8);
            }
            CP_COMMIT;
        }
        cp_wait_dyn(7);       // Q1 done; V chunks may pend
        __syncthreads();
    } else {
        // G0: Q1 + K chunk 0
        if (tid < 256) {
            int row = tid >> 3, c8 = tid & 7;
            cpa16(Q1s + row * 72 + c8 * 8, Q1g + row * 64 + c8 * 8);
        }
#pragma unroll
        for (int r = 0; r < 2; r++) {
            int op = tid + r * 512, row = op >> 3, cc = op & 7;
            cpa16(Ks + row * 72 + cc * 8, Kg + row * 64 + cc * 8);
        }
        CP_COMMIT;
        CP_WAIT0;
        __syncthreads();
    }

    // A fragments: Q1 rows mw*16..+15, 4 k16 steps
    unsigned afr[4][4];
#pragma unroll
    for (int ks = 0; ks < 4; ks++)
        ldsm4(afr[ks], Q1s + (mw * 16 + (lane & 15)) * 72 + (lane >> 4) * 8 + ks * 16);

    // ---- S = Q1*K^T. Warp's cols: {c*128 + gw*16 + 0..15}, j = c*2 + half
    float acc[16][4] = {};
    for (int c = 0; c < 8; c++) {
        const __half* Bb;
        if (!phase) {
            cp_wait_dyn(7 - c);          // V chunk c landed
            __syncthreads();
            Bb = Vs + c * 128 * 72;
        } else {
            cp_wait_dyn(c == 0 ? 0 : 1); // K_c landed (2nd-newest group)
            __syncthreads();             // also: all warps done with prev K buffer
            if (c < 7) {                 // prefetch K chunk c+1
#pragma unroll
                for (int r = 0; r < 2; r++) {
                    int op = tid + r * 512, row = op >> 3, cc = op & 7;
                    cpa16(Ks + (((c + 1) & 1) * 128 + row) * 72 + cc * 8,
                          Kg + ((size_t)((c + 1) * 128 + row)) * 64 + cc * 8);
                }
                CP_COMMIT;
            }
            {                            // stream V chunk c (used only by O-GEMM)
#pragma unroll
                for (int r = 0; r < 2; r++) {
                    int op = tid + r * 512, row = op >> 3, cc = op & 7;
                    cpa16(Vs + (c * 128 + row) * 72 + cc * 8,
                          Vg + ((size_t)(c * 128 + row)) * 64 + cc * 8);
                }
                CP_COMMIT;
            }
            Bb = Ks + (c & 1) * 128 * 72;
        }
        unsigned b[4][4];
#pragma unroll
        for (int ks = 0; ks < 4; ks++)
            ldsm4(b[ks], Bb + (gw * 16 + (lane & 15)) * 72 + (lane >> 4) * 8 + ks * 16);
#pragma unroll
        for (int ks = 0; ks < 4; ks++) {
            mma16(acc[c * 2],     afr[ks], b[ks][0], b[ks][2]);
            mma16(acc[c * 2 + 1], afr[ks], b[ks][1], b[ks][3]);
        }
    }

    // ---- softmax without max subtraction (args ~N(0,0.45), |arg| < ~3)
    const float sc = 1.0f / 1018.0f;
    float l0 = 0.f, l1 = 0.f;
#pragma unroll
    for (int j = 0; j < 16; j++) {
        int gcol = (j >> 1) * 128 + gw * 16 + (j & 1) * 8 + 2 * qi;
        float e0 = (gcol < HO)     ? __expf(acc[j][0] * sc) : 0.f;
        float e1 = (gcol + 1 < HO) ? __expf(acc[j][1] * sc) : 0.f;
        float e2 = (gcol < HO)     ? __expf(acc[j][2] * sc) : 0.f;
        float e3 = (gcol + 1 < HO) ? __expf(acc[j][3] * sc) : 0.f;
        acc[j][0] = e0; acc[j][1] = e1; acc[j][2] = e2; acc[j][3] = e3;
        l0 += e0 + e1; l1 += e2 + e3;
    }
#pragma unroll
    for (int o = 1; o <= 2; o <<= 1) {
        l0 += __shfl_xor_sync(~0u, l0, o);
        l1 += __shfl_xor_sync(~0u, l1, o);
    }
    if (qi == 0) {
        red[gw * 32 + mw * 16 + gq] = l0;
        red[gw * 32 + mw * 16 + gq + 8] = l1;
    }
    __syncthreads();
    if (gw == 0 && qi == 0) {
        float L0 = 0.f, L1 = 0.f;
#pragma unroll
        for (int g2 = 0; g2 < 8; g2++) {
            L0 += red[g2 * 32 + mw * 16 + gq];
            L1 += red[g2 * 32 + mw * 16 + gq + 8];
        }
        lsm[mw * 16 + gq] = L0;
        lsm[mw * 16 + gq + 8] = L1;
    }

    // ---- drain V stream (phase 1) before reading Vs for O-GEMM
    CP_WAIT0;
    __syncthreads();

    // ---- O = P*V partial over this warp's 128 g-cols; P stays in registers
    float od[8][4] = {};
#pragma unroll
    for (int c = 0; c < 8; c++) {
        int grow = c * 128 + gw * 16;
        unsigned a[4];
        a[0] = h2u(acc[c * 2][0],     acc[c * 2][1]);
        a[1] = h2u(acc[c * 2][2],     acc[c * 2][3]);
        a[2] = h2u(acc[c * 2 + 1][0], acc[c * 2 + 1][1]);
        a[3] = h2u(acc[c * 2 + 1][2], acc[c * 2 + 1][3]);
#pragma unroll
        for (int dv = 0; dv < 4; dv++) {
            unsigned b[4];
            ldsm4t(b, Vs + (grow + (lane & 15)) * 72 + (lane >> 4) * 8 + dv * 16);
            mma16(od[dv * 2],     a, b[0], b[1]);
            mma16(od[dv * 2 + 1], a, b[2], b[3]);
        }
    }

    // ---- cross-warp reduce over the 8 g-groups (Obuf overlays Vs), epilogue
    __syncthreads();
#pragma unroll
    for (int nf = 0; nf < 8; nf++) {
        int row = mw * 16 + gq, d = nf * 8 + 2 * qi;
        *(float2*)&Obuf[(gw * 32 + row) * 64 + d] = make_float2(od[nf][0], od[nf][1]);
        *(float2*)&Obuf[(gw * 32 + row + 8) * 64 + d] = make_float2(od[nf][2], od[nf][3]);
    }
    __syncthreads();
    {
        int row = tid >> 4, d0 = (tid & 15) * 4;
        float inv = 1.0f / lsm[row];
        int h = h0 + row;
        const int nb = slice >> 5, f = slice & 31;
#pragma unroll
        for (int dd = 0; dd < 4; dd++) {
            int d = d0 + dd;
            float v = 0.f;
#pragma unroll
            for (int g2 = 0; g2 < 8; g2++) v += Obuf[(g2 * 32 + row) * 64 + d];
            v *= inv;
            if (!phase)
                g_p1h[((size_t)slice * HP + h) * DD + d] = __float2half(v);
            if (h < HO)
                out[((size_t)(nb * HO + h) * FB + f) * DD + d] = tanhf(v);
        }
    }
}

// ---------------------------------------------------------------------------
extern "C" void kernel_launch(void* const* d_in, const int* in_sizes, int n_in,
                              void* d_out, int out_size)
{
    const float* prot1 = (const float*)d_in[0];
    const float* prot2 = (const float*)d_in[1];
    const float* W     = (const float*)d_in[2];
    float* out = (float*)d_out;

    cudaFuncSetAttribute(fused_kernel, cudaFuncAttributeMaxDynamicSharedMemorySize,
                         SMEM_FUSED);

    proj_kernel<<<dim3(16, FB, 2 * NB), 256>>>(prot1, prot2, W);
    fused_kernel<<<dim3(32, NSLICE), 512, SMEM_FUSED>>>(out, 0);
    fused_kernel<<<dim3(32, NSLICE), 512, SMEM_FUSED>>>(out + (size_t)NB * HO * FB * DD, 1);
}